// round 16
// baseline (speedup 1.0000x reference)
#include <cuda_runtime.h>
#include <cstdlib>
#include <cstdint>
#include <cfloat>

#define BB 8
#define NN 2048
#define KNB 20
#define NEGS 0.2f
#define EPSB 1e-5f

__attribute__((constructor)) static void _eager_load(){ setenv("CUDA_MODULE_LOADING","EAGER",0); }

// ------------------------- scratch (device globals) -------------------------
__device__ float g_xT  [(size_t)BB*NN*256];
__device__ float g_xx  [BB*NN];
__device__ float g_dist[(size_t)BB*NN*NN];
__device__ int   g_idx [(size_t)BB*NN*KNB];
__device__ float g_kmax[(size_t)BB*256*NN];
__device__ float g_kmin[(size_t)BB*256*NN];
__device__ float g_ksum[(size_t)BB*256*NN];
__device__ float g_ksq [(size_t)BB*256*NN];
__device__ float g_base[(size_t)BB*256*NN];   // (W_b - W_a) @ ctr
__device__ float g_Wd  [256*128];             // W[:,C:2C] - W[:,:C]
__device__ float g_xcat[(size_t)BB*512*NN];
__device__ float g_h5  [(size_t)BB*1024*NN];
__device__ float g_hb1 [(size_t)BB*256*NN];
__device__ float g_hb2 [(size_t)BB*256*NN];
__device__ float g_hb3 [(size_t)BB*128*NN];
__device__ float g_glob[BB*1088];
__device__ float g_b207[BB*256];
__device__ float g_prm [2048];

// ------------------------- TF32 helpers -------------------------
__device__ __forceinline__ uint32_t f2tf32(float x){
    uint32_t u; asm("cvt.rna.tf32.f32 %0, %1;" : "=r"(u) : "f"(x)); return u;
}
__device__ __forceinline__ void mma_tf32(float* d, const uint32_t* a, const uint32_t* b){
    asm volatile("mma.sync.aligned.m16n8k8.row.col.f32.tf32.tf32.f32 "
        "{%0,%1,%2,%3}, {%4,%5,%6,%7}, {%8,%9}, {%0,%1,%2,%3};"
        : "+f"(d[0]),"+f"(d[1]),"+f"(d[2]),"+f"(d[3])
        : "r"(a[0]),"r"(a[1]),"r"(a[2]),"r"(a[3]), "r"(b[0]),"r"(b[1]));
}

// ------------------------- generic fp32 GEMM (pipelined) ---------------------
// (used only for the small "base" GEMMs in the split edge path)
template<bool BT, int MODE>
__global__ void __launch_bounds__(256,2) k_gemm(
    int M, int Ncol, int Kd,
    const float* __restrict__ A, int lda, size_t asb,
    const float* __restrict__ Bp, int ldb, size_t bsb,
    float* __restrict__ Cp, size_t csb,
    const float* __restrict__ e0)
{
    const int BM=128, BN=128, BK=16;
    __shared__ float As[2][BK][BM+4];
    __shared__ float Bs[2][BK][BN+4];
    int b  = blockIdx.z;
    int m0 = blockIdx.y*BM, n0 = blockIdx.x*BN;
    A  += (size_t)b*asb;
    Bp += (size_t)b*bsb;
    Cp += (size_t)b*csb;
    int tid = threadIdx.x;
    int tx = tid%16, ty = tid/16;

    float acc[8][8];
    #pragma unroll
    for(int i=0;i<8;i++)
        #pragma unroll
        for(int j=0;j<8;j++) acc[i][j]=0.f;

    float ra[8], rb[8];

    auto fetchA = [&](int k0){
        #pragma unroll
        for(int i=0;i<8;i++){
            int e = tid + 256*i;
            int kk=e%BK, mm=e/BK;
            int gm=m0+mm, gk=k0+kk;
            ra[i] = (gm<M && gk<Kd) ? A[(size_t)gm*lda+gk] : 0.f;
        }
    };
    auto fetchB = [&](int k0){
        if(!BT){
            #pragma unroll
            for(int i=0;i<8;i++){
                int e = tid + 256*i;
                int kk=e%BK, nn=e/BK;
                int gn=n0+nn, gk=k0+kk;
                rb[i] = (gn<Ncol && gk<Kd) ? Bp[(size_t)gn*ldb+gk] : 0.f;
            }
        } else {
            #pragma unroll
            for(int i=0;i<8;i++){
                int e = tid + 256*i;
                int nn=e%BN, kk=e/BN;
                int gn=n0+nn, gk=k0+kk;
                rb[i] = (gn<Ncol && gk<Kd) ? Bp[(size_t)gk*ldb+gn] : 0.f;
            }
        }
    };
    auto store = [&](int buf){
        #pragma unroll
        for(int i=0;i<8;i++){
            int e = tid + 256*i;
            As[buf][e%BK][e/BK] = ra[i];
        }
        if(!BT){
            #pragma unroll
            for(int i=0;i<8;i++){
                int e = tid + 256*i;
                Bs[buf][e%BK][e/BK] = rb[i];
            }
        } else {
            #pragma unroll
            for(int i=0;i<8;i++){
                int e = tid + 256*i;
                Bs[buf][e/BN][e%BN] = rb[i];
            }
        }
    };

    int nk = (Kd + BK - 1)/BK;
    fetchA(0); fetchB(0);
    store(0);
    __syncthreads();

    for(int t=0;t<nk;t++){
        int cur = t&1;
        if(t+1<nk){ fetchA((t+1)*BK); fetchB((t+1)*BK); }
        #pragma unroll
        for(int kk=0;kk<BK;kk++){
            float a8[8], b8[8];
            #pragma unroll
            for(int i=0;i<8;i++) a8[i]=As[cur][kk][ty*8+i];
            #pragma unroll
            for(int j=0;j<8;j++) b8[j]=Bs[cur][kk][tx*8+j];
            #pragma unroll
            for(int i=0;i<8;i++)
                #pragma unroll
                for(int j=0;j<8;j++) acc[i][j] = __fmaf_rn(a8[i], b8[j], acc[i][j]);
        }
        if(t+1<nk){
            __syncthreads();
            store(1-cur);
            __syncthreads();
        }
    }

    #pragma unroll
    for(int i=0;i<8;i++){
        int gm = m0+ty*8+i;
        if(gm>=M) continue;
        #pragma unroll
        for(int j=0;j<8;j++){
            int gn = n0+tx*8+j;
            if(gn>=Ncol) continue;
            float v = acc[i][j];
            if(MODE==2) v = __fadd_rn(v, e0[(size_t)b*M+gm]);
            Cp[(size_t)gm*Ncol + gn] = v;
        }
    }
}

// ------------------- 3xTF32 tensor-core tail GEMM ---------------------------
template<int MODE>
__global__ void __launch_bounds__(256,3) k_tgemm(
    int M, int Kd,
    const float* __restrict__ A, int lda,
    const float* __restrict__ Bp, size_t bsb, int ldb,
    float* __restrict__ Cp, size_t csb,
    const float* __restrict__ e0)
{
    const int BM=128, BN=64, BK=16;
    __shared__ float Ah[BM][20], Al[BM][20];
    __shared__ float Bh[BK][72], Bl[BK][72];
    int b  = blockIdx.z;
    int m0 = blockIdx.y*BM, n0 = blockIdx.x*BN;
    Bp += (size_t)b*bsb;
    Cp += (size_t)b*csb;
    int tid = threadIdx.x;
    int lane = tid&31, warp = tid>>5;
    int wm = warp>>1, wn = warp&1;
    int gID = lane>>2, tig = lane&3;

    float acc[2][4][4];
    #pragma unroll
    for(int i=0;i<2;i++)
        #pragma unroll
        for(int j=0;j<4;j++)
            #pragma unroll
            for(int q=0;q<4;q++) acc[i][j][q]=0.f;

    int nk = Kd/BK;
    for(int t=0;t<nk;t++){
        int k0 = t*BK;
        #pragma unroll
        for(int i=0;i<8;i++){
            int e = tid + 256*i;
            int k = e&15, m = e>>4;
            int gm = m0+m;
            float x = (gm<M) ? A[(size_t)gm*lda + k0+k] : 0.f;
            float hi = __uint_as_float(f2tf32(x));
            float lo = __uint_as_float(f2tf32(__fsub_rn(x, hi)));
            Ah[m][k] = hi; Al[m][k] = lo;
        }
        #pragma unroll
        for(int i=0;i<4;i++){
            int e = tid + 256*i;
            int n = e&63, k = e>>6;
            float x = Bp[(size_t)(k0+k)*ldb + n0+n];
            float hi = __uint_as_float(f2tf32(x));
            float lo = __uint_as_float(f2tf32(__fsub_rn(x, hi)));
            Bh[k][n] = hi; Bl[k][n] = lo;
        }
        __syncthreads();
        #pragma unroll
        for(int kk=0;kk<BK;kk+=8){
            uint32_t afh[2][4], afl[2][4], bfh[4][2], bfl[4][2];
            #pragma unroll
            for(int mt=0;mt<2;mt++){
                int row = wm*32 + mt*16;
                afh[mt][0] = __float_as_uint(Ah[row+gID  ][kk+tig  ]);
                afh[mt][1] = __float_as_uint(Ah[row+gID+8][kk+tig  ]);
                afh[mt][2] = __float_as_uint(Ah[row+gID  ][kk+tig+4]);
                afh[mt][3] = __float_as_uint(Ah[row+gID+8][kk+tig+4]);
                afl[mt][0] = __float_as_uint(Al[row+gID  ][kk+tig  ]);
                afl[mt][1] = __float_as_uint(Al[row+gID+8][kk+tig  ]);
                afl[mt][2] = __float_as_uint(Al[row+gID  ][kk+tig+4]);
                afl[mt][3] = __float_as_uint(Al[row+gID+8][kk+tig+4]);
            }
            #pragma unroll
            for(int nt=0;nt<4;nt++){
                int col = wn*32 + nt*8 + gID;
                bfh[nt][0] = __float_as_uint(Bh[kk+tig  ][col]);
                bfh[nt][1] = __float_as_uint(Bh[kk+tig+4][col]);
                bfl[nt][0] = __float_as_uint(Bl[kk+tig  ][col]);
                bfl[nt][1] = __float_as_uint(Bl[kk+tig+4][col]);
            }
            #pragma unroll
            for(int mt=0;mt<2;mt++)
                #pragma unroll
                for(int nt=0;nt<4;nt++){
                    mma_tf32(acc[mt][nt], afl[mt], bfh[nt]);
                    mma_tf32(acc[mt][nt], afh[mt], bfl[nt]);
                    mma_tf32(acc[mt][nt], afh[mt], bfh[nt]);
                }
        }
        __syncthreads();
    }

    #pragma unroll
    for(int mt=0;mt<2;mt++){
        int r0 = m0 + wm*32 + mt*16 + gID;
        int r1 = r0 + 8;
        #pragma unroll
        for(int nt=0;nt<4;nt++){
            int c0 = n0 + wn*32 + nt*8 + tig*2;
            float v0=acc[mt][nt][0], v1=acc[mt][nt][1], v2=acc[mt][nt][2], v3=acc[mt][nt][3];
            if(MODE==2){
                if(r0<M){ float e=e0[(size_t)b*M+r0]; v0=__fadd_rn(v0,e); v1=__fadd_rn(v1,e); }
                if(r1<M){ float e=e0[(size_t)b*M+r1]; v2=__fadd_rn(v2,e); v3=__fadd_rn(v3,e); }
            }
            if(r0<M){ Cp[(size_t)r0*NN + c0] = v0; Cp[(size_t)r0*NN + c0+1] = v1; }
            if(r1<M){ Cp[(size_t)r1*NN + c0] = v2; Cp[(size_t)r1*NN + c0+1] = v3; }
        }
    }
}

// ------- 3xTF32 fused edge-conv GEMM + in-fragment k-reduce (layers 2-4) ----
// h[o, n*20+k] = sum_c W_a[o,c]*nbr[n,k,c]; + base[o,n]; reduce over k=20.
// Warp tile 32m x 40n = 2 points; block = WM x WN warps.
template<int C, int WM, int WN>
__global__ void __launch_bounds__(WM*WN*32,2) k_egemm_tc(
    int O,
    const float* __restrict__ A,          // W [O, 2C], first C cols used
    const float* __restrict__ xTp,        // [B, N, C]
    const int*   __restrict__ idxp)       // [B, N, K]
{
    const int BM=WM*32, BN=WN*40, BK=16, T=WM*WN*32, PTS=WN*2;
    __shared__ float Ah[BM][BK+4], Al[BM][BK+4];
    __shared__ float Bh[BK][BN+9], Bl[BK][BN+9];
    __shared__ int   s_moff[BN];
    int b  = blockIdx.z;
    int m0 = blockIdx.y*BM;
    int p0 = blockIdx.x*PTS;
    xTp  += (size_t)b*NN*C;
    idxp += (size_t)b*NN*KNB;
    int tid=threadIdx.x, lane=tid&31, warp=tid>>5;
    int wm=warp/WN, wn=warp%WN;
    int gID=lane>>2, tig=lane&3;

    if(tid<BN){
        int pt=tid/KNB, kq=tid-pt*KNB;
        s_moff[tid]=idxp[(size_t)(p0+pt)*KNB+kq]*C;
    }
    __syncthreads();

    float acc[2][5][4];
    #pragma unroll
    for(int i=0;i<2;i++)
        #pragma unroll
        for(int j=0;j<5;j++)
            #pragma unroll
            for(int q=0;q<4;q++) acc[i][j][q]=0.f;

    const int NK=C/BK;
    for(int t=0;t<NK;t++){
        int k0=t*BK;
        #pragma unroll
        for(int e=tid;e<BM*BK;e+=T){
            int k=e&15, m=e>>4;
            float x=A[(size_t)(m0+m)*(2*C)+k0+k];
            float hi=__uint_as_float(f2tf32(x));
            float lo=__uint_as_float(f2tf32(__fsub_rn(x,hi)));
            Ah[m][k]=hi; Al[m][k]=lo;
        }
        #pragma unroll
        for(int e=tid;e<BN*BK;e+=T){
            int k=e&15, nn=e>>4;
            float x=xTp[s_moff[nn]+k0+k];
            float hi=__uint_as_float(f2tf32(x));
            float lo=__uint_as_float(f2tf32(__fsub_rn(x,hi)));
            Bh[k][nn]=hi; Bl[k][nn]=lo;
        }
        __syncthreads();
        #pragma unroll
        for(int kk=0;kk<BK;kk+=8){
            uint32_t afh[2][4], afl[2][4], bfh[5][2], bfl[5][2];
            #pragma unroll
            for(int mt=0;mt<2;mt++){
                int row = wm*32 + mt*16;
                afh[mt][0]=__float_as_uint(Ah[row+gID  ][kk+tig  ]);
                afh[mt][1]=__float_as_uint(Ah[row+gID+8][kk+tig  ]);
                afh[mt][2]=__float_as_uint(Ah[row+gID  ][kk+tig+4]);
                afh[mt][3]=__float_as_uint(Ah[row+gID+8][kk+tig+4]);
                afl[mt][0]=__float_as_uint(Al[row+gID  ][kk+tig  ]);
                afl[mt][1]=__float_as_uint(Al[row+gID+8][kk+tig  ]);
                afl[mt][2]=__float_as_uint(Al[row+gID  ][kk+tig+4]);
                afl[mt][3]=__float_as_uint(Al[row+gID+8][kk+tig+4]);
            }
            #pragma unroll
            for(int nt=0;nt<5;nt++){
                int col = wn*40 + nt*8 + gID;
                bfh[nt][0]=__float_as_uint(Bh[kk+tig  ][col]);
                bfh[nt][1]=__float_as_uint(Bh[kk+tig+4][col]);
                bfl[nt][0]=__float_as_uint(Bl[kk+tig  ][col]);
                bfl[nt][1]=__float_as_uint(Bl[kk+tig+4][col]);
            }
            #pragma unroll
            for(int mt=0;mt<2;mt++)
                #pragma unroll
                for(int nt=0;nt<5;nt++){
                    mma_tf32(acc[mt][nt], afl[mt], bfh[nt]);
                    mma_tf32(acc[mt][nt], afh[mt], bfl[nt]);
                    mma_tf32(acc[mt][nt], afh[mt], bfh[nt]);
                }
        }
        __syncthreads();
    }

    // epilogue: per-row per-point partials (+base), quad shfl reduce over tig
    int pA = p0 + wn*2, pB = pA + 1;
    #pragma unroll
    for(int mt=0;mt<2;mt++){
        #pragma unroll
        for(int half=0;half<2;half++){
            int gm = m0 + wm*32 + mt*16 + gID + half*8;
            float bsA = g_base[((size_t)b*O+gm)*NN + pA];
            float bsB = g_base[((size_t)b*O+gm)*NN + pB];
            float mxA=-FLT_MAX, mnA=FLT_MAX, smA=0.f, sqA=0.f;
            float mxB=-FLT_MAX, mnB=FLT_MAX, smB=0.f, sqB=0.f;
            #pragma unroll
            for(int nt=0;nt<5;nt++){
                #pragma unroll
                for(int q=0;q<2;q++){
                    int col = nt*8 + tig*2 + q;          // 0..39 within warp tile
                    float a = acc[mt][nt][half*2+q];
                    if(col<20){
                        float h = __fadd_rn(a, bsA);
                        mxA=fmaxf(mxA,h); mnA=fminf(mnA,h);
                        smA=__fadd_rn(smA,h); sqA=__fmaf_rn(h,h,sqA);
                    } else {
                        float h = __fadd_rn(a, bsB);
                        mxB=fmaxf(mxB,h); mnB=fminf(mnB,h);
                        smB=__fadd_rn(smB,h); sqB=__fmaf_rn(h,h,sqB);
                    }
                }
            }
            #pragma unroll
            for(int o=1;o<=2;o<<=1){
                mxA=fmaxf(mxA,__shfl_xor_sync(0xffffffffu,mxA,o));
                mnA=fminf(mnA,__shfl_xor_sync(0xffffffffu,mnA,o));
                smA=__fadd_rn(smA,__shfl_xor_sync(0xffffffffu,smA,o));
                sqA=__fadd_rn(sqA,__shfl_xor_sync(0xffffffffu,sqA,o));
                mxB=fmaxf(mxB,__shfl_xor_sync(0xffffffffu,mxB,o));
                mnB=fminf(mnB,__shfl_xor_sync(0xffffffffu,mnB,o));
                smB=__fadd_rn(smB,__shfl_xor_sync(0xffffffffu,smB,o));
                sqB=__fadd_rn(sqB,__shfl_xor_sync(0xffffffffu,sqB,o));
            }
            if(tig==0){
                size_t ba = ((size_t)b*O+gm)*NN + pA;
                size_t bb2 = ((size_t)b*O+gm)*NN + pB;
                g_kmax[ba]=mxA; g_kmin[ba]=mnA; g_ksum[ba]=smA; g_ksq[ba]=sqA;
                g_kmax[bb2]=mxB; g_kmin[bb2]=mnB; g_ksum[bb2]=smB; g_ksq[bb2]=sqB;
            }
        }
    }
}

// -------- symmetric dist GEMM (layers 2-4) --------------------------------
__global__ void __launch_bounds__(256,2) k_dgemm(
    int Kd, const float* __restrict__ Xp, const float* __restrict__ e0)
{
    const int BK=16;
    if(blockIdx.x < blockIdx.y) return;
    __shared__ float pool[8448];
    #define ASM(buf,kk,mm) pool[(buf)*2112 + (kk)*132 + (mm)]
    #define BSM(buf,kk,nn) pool[4224 + (buf)*2112 + (kk)*132 + (nn)]
    int b  = blockIdx.z;
    int m0 = blockIdx.y*128, n0 = blockIdx.x*128;
    const float* A = Xp + (size_t)b*NN*Kd;
    float* Cp = g_dist + (size_t)b*NN*NN;
    const float* xxr = e0 + (size_t)b*NN;
    int tid = threadIdx.x;
    int tx = tid%16, ty = tid/16;

    float acc[8][8];
    #pragma unroll
    for(int i=0;i<8;i++)
        #pragma unroll
        for(int j=0;j<8;j++) acc[i][j]=0.f;

    float ra[8], rb[8];
    auto fetchA = [&](int k0){
        #pragma unroll
        for(int i=0;i<8;i++){
            int e = tid + 256*i;
            int kk=e&15, mm=e>>4;
            int gk=k0+kk;
            ra[i] = (gk<Kd) ? A[(size_t)(m0+mm)*Kd+gk] : 0.f;
        }
    };
    auto fetchB = [&](int k0){
        #pragma unroll
        for(int i=0;i<8;i++){
            int e = tid + 256*i;
            int kk=e&15, nn=e>>4;
            int gk=k0+kk;
            rb[i] = (gk<Kd) ? A[(size_t)(n0+nn)*Kd+gk] : 0.f;
        }
    };
    auto store = [&](int buf){
        #pragma unroll
        for(int i=0;i<8;i++){
            int e = tid + 256*i;
            ASM(buf, e&15, e>>4) = ra[i];
        }
        #pragma unroll
        for(int i=0;i<8;i++){
            int e = tid + 256*i;
            BSM(buf, e&15, e>>4) = rb[i];
        }
    };

    int nk = (Kd + BK - 1)/BK;
    fetchA(0); fetchB(0);
    store(0);
    __syncthreads();
    for(int t=0;t<nk;t++){
        int cur = t&1;
        if(t+1<nk){ fetchA((t+1)*BK); fetchB((t+1)*BK); }
        #pragma unroll
        for(int kk=0;kk<BK;kk++){
            float a8[8], b8[8];
            #pragma unroll
            for(int i=0;i<8;i++) a8[i]=ASM(cur,kk,ty*8+i);
            #pragma unroll
            for(int j=0;j<8;j++) b8[j]=BSM(cur,kk,tx*8+j);
            #pragma unroll
            for(int i=0;i<8;i++)
                #pragma unroll
                for(int j=0;j<8;j++) acc[i][j] = __fmaf_rn(a8[i], b8[j], acc[i][j]);
        }
        if(t+1<nk){
            __syncthreads();
            store(1-cur);
            __syncthreads();
        }
    }

    #pragma unroll
    for(int i=0;i<8;i++){
        int gm = m0+ty*8+i;
        float xm = xxr[gm];
        #pragma unroll
        for(int j=0;j<8;j++){
            int gn = n0+tx*8+j;
            float v = __fsub_rn(__fsub_rn(__fmul_rn(2.0f, acc[i][j]), xm), xxr[gn]);
            acc[i][j] = v;
            Cp[(size_t)gm*NN + gn] = v;
        }
    }
    if(blockIdx.x > blockIdx.y){
        for(int c=0;c<4;c++){
            __syncthreads();
            if((tx>>2)==c){
                int tl = tx&3;
                #pragma unroll
                for(int i=0;i<8;i++)
                    #pragma unroll
                    for(int j=0;j<8;j++)
                        pool[(tl*8+j)*132 + ty*8+i] = acc[i][j];
            }
            __syncthreads();
            #pragma unroll
            for(int q=0;q<16;q++){
                int e = tid + 256*q;
                int rr=e>>7, cc=e&127;
                Cp[(size_t)(n0+c*32+rr)*NN + m0+cc] = pool[rr*132+cc];
            }
        }
    }
    #undef ASM
    #undef BSM
}

// ------- L1 exact fused edge-conv GEMM + k-reduce (full 2C path, fp32) ------
template<int C, int BM, int MAXB>
__global__ void __launch_bounds__(256,MAXB) k_egemm_t(
    int M,
    const float* __restrict__ A,
    const float* __restrict__ xTp,
    const int*   __restrict__ idxp)
{
    const int BN=160, BK=16;
    const int Kd = 2*C;
    const int NK = (Kd + BK - 1)/BK;
    const int TM = BM/16;
    const int NA = BM*BK/256;
    __shared__ float As[2][BK][BM+4];
    __shared__ float Bs[2][BK][BN+4];
    __shared__ int   s_moff[BN];
    __shared__ int   s_poff[BN];
    int b  = blockIdx.z;
    int m0 = blockIdx.y*BM;
    int p0 = blockIdx.x*8;
    xTp  += (size_t)b*NN*C;
    idxp += (size_t)b*NN*KNB;
    int tid = threadIdx.x;
    int tx = tid%16, ty = tid/16;

    if(tid < BN){
        int pt = tid/KNB;
        int kq = tid - pt*KNB;
        s_poff[tid] = (p0+pt)*C;
        s_moff[tid] = idxp[(size_t)(p0+pt)*KNB + kq]*C;
    }
    __syncthreads();

    float acc[TM][10];
    #pragma unroll
    for(int i=0;i<TM;i++)
        #pragma unroll
        for(int j=0;j<10;j++) acc[i][j]=0.f;

    float ra[NA], rb[10];
    int kkme = tid & 15;

    auto fetchA = [&](int k0){
        #pragma unroll
        for(int i=0;i<NA;i++){
            int e = tid + 256*i;
            int kk=e&15, mm=e>>4;
            int gk=k0+kk;
            ra[i] = (gk<Kd) ? A[(size_t)(m0+mm)*Kd+gk] : 0.f;
        }
    };
    auto fetchB = [&](int k0){
        int gk = k0 + kkme;
        #pragma unroll
        for(int i=0;i<10;i++){
            int nn = (tid>>4) + 16*i;
            float val = 0.f;
            if(gk < Kd){
                int cc = (gk<C) ? gk : gk-C;
                float ctr = xTp[s_poff[nn] + cc];
                if(gk<C) val = __fsub_rn(xTp[s_moff[nn] + cc], ctr);
                else     val = ctr;
            }
            rb[i] = val;
        }
    };
    auto store = [&](int buf){
        #pragma unroll
        for(int i=0;i<NA;i++){
            int e = tid + 256*i;
            As[buf][e&15][e>>4] = ra[i];
        }
        #pragma unroll
        for(int i=0;i<10;i++){
            int nn = (tid>>4) + 16*i;
            Bs[buf][kkme][nn] = rb[i];
        }
    };

    fetchA(0); fetchB(0);
    store(0);
    __syncthreads();

    #pragma unroll 1
    for(int t=0;t<NK;t++){
        int cur = t&1;
        if(t+1<NK){ fetchA((t+1)*BK); fetchB((t+1)*BK); }
        #pragma unroll
        for(int kk=0;kk<BK;kk++){
            float am[TM], b10[10];
            #pragma unroll
            for(int i=0;i<TM;i++) am[i]=As[cur][kk][ty*TM+i];
            #pragma unroll
            for(int j=0;j<10;j++) b10[j]=Bs[cur][kk][tx*10+j];
            #pragma unroll
            for(int i=0;i<TM;i++)
                #pragma unroll
                for(int j=0;j<10;j++) acc[i][j] = __fmaf_rn(am[i], b10[j], acc[i][j]);
        }
        if(t+1<NK){
            __syncthreads();
            store(1-cur);
            __syncthreads();
        }
    }

    int O = M;
    #pragma unroll
    for(int i=0;i<TM;i++){
        float mx=-FLT_MAX, mn=FLT_MAX, sm=0.f, sq=0.f;
        #pragma unroll
        for(int j=0;j<10;j++){
            float h = acc[i][j];
            mx = fmaxf(mx,h); mn = fminf(mn,h);
            sm = __fadd_rn(sm,h); sq = __fmaf_rn(h,h,sq);
        }
        #pragma unroll
        for(int j=0;j<10;j++){
            float h = __shfl_xor_sync(0xffffffffu, acc[i][j], 1);
            mx = fmaxf(mx,h); mn = fminf(mn,h);
            sm = __fadd_rn(sm,h); sq = __fmaf_rn(h,h,sq);
        }
        int gm = m0 + ty*TM + i;
        if((tx&1)==0){
            int point = p0 + (tx>>1);
            size_t base = ((size_t)b*O + gm)*NN + point;
            g_kmax[base]=mx; g_kmin[base]=mn; g_ksum[base]=sm; g_ksq[base]=sq;
        }
    }
}

// ------------------------- small kernels -------------------------

__global__ void k_tin(const float* __restrict__ x){
    int i = blockIdx.x*blockDim.x + threadIdx.x;
    if(i >= BB*NN*3) return;
    int c = i%3; int n = (i/3)%NN; int b = i/(3*NN);
    g_xT[i] = x[((size_t)b*3 + c)*NN + n];
}

__global__ void k_xx(int C){
    int p = blockIdx.x*blockDim.x + threadIdx.x;
    if(p >= BB*NN) return;
    const float* v = g_xT + (size_t)p*C;
    float s = 0.f;
    for(int c=0;c<C;c++) s = __fadd_rn(s, __fmul_rn(v[c], v[c]));
    g_xx[p] = s;
}

__global__ void k_wdiff(const float* __restrict__ W, int O, int C){
    int i = blockIdx.x*blockDim.x + threadIdx.x;
    if(i >= O*C) return;
    int o = i/C, c = i%C;
    g_Wd[i] = __fsub_rn(W[(size_t)o*2*C + C + c], W[(size_t)o*2*C + c]);
}

// shared top-k selection body (given v[8] per thread).
template<int FUSED3>
__device__ __forceinline__ void topk_select(
    float* v, int tid, int lane, int w, int n, int bq,
    const float* __restrict__ X3, float xxn, const float* __restrict__ xxr)
{
    __shared__ float swmx[8], swmn[8];
    __shared__ int hist8[8][256];
    __shared__ int hist[256];
    __shared__ unsigned long long cand[256];
    __shared__ int s_cnt, s_B, s_size;
    __shared__ float s_lo, s_hi;
    int base = tid*8;

    float mx=v[0], mn=v[0];
    #pragma unroll
    for(int t=1;t<8;t++){ mx=fmaxf(mx,v[t]); mn=fminf(mn,v[t]); }
    #pragma unroll
    for(int o=16;o;o>>=1){
        mx=fmaxf(mx,__shfl_xor_sync(0xffffffffu,mx,o));
        mn=fminf(mn,__shfl_xor_sync(0xffffffffu,mn,o));
    }
    if(lane==0){ swmx[w]=mx; swmn[w]=mn; }
    #pragma unroll
    for(int q=0;q<8;q++) hist8[q][tid]=0;
    __syncthreads();
    if(tid==0){
        float hx=swmx[0], hn=swmn[0];
        #pragma unroll
        for(int q=1;q<8;q++){ hx=fmaxf(hx,swmx[q]); hn=fminf(hn,swmn[q]); }
        s_lo=hn; s_hi=hx; s_cnt=0;
    }
    __syncthreads();
    float lo=s_lo, hi=s_hi;
    float scale = (hi>lo) ? 255.0f/(hi-lo) : 0.0f;
    int bk[8];
    #pragma unroll
    for(int t=0;t<8;t++){
        int bb = (int)((v[t]-lo)*scale);
        bb = max(0, min(255, bb));
        bk[t]=bb;
        atomicAdd(&hist8[w][bb],1);
    }
    __syncthreads();
    {
        int hsum = 0;
        #pragma unroll
        for(int q=0;q<8;q++) hsum += hist8[q][tid];
        hist[tid] = hsum;
    }
    __syncthreads();
    if(w==0){
        int cs = 0;
        #pragma unroll
        for(int t=0;t<8;t++) cs += hist[lane*8+t];
        int rs = cs;
        #pragma unroll
        for(int o=1;o<32;o<<=1){
            int t2 = __shfl_down_sync(0xffffffffu, rs, o);
            if(lane+o<32) rs += t2;
        }
        int sufx = rs - cs;
        if(rs >= KNB && sufx < KNB){
            int run = sufx, Bv = lane*8;
            for(int j=7;j>=0;j--){
                run += hist[lane*8+j];
                if(run >= KNB){ Bv = lane*8+j; break; }
            }
            s_B = Bv;
        }
    }
    __syncthreads();
    int B = s_B;
    #pragma unroll
    for(int t=0;t<8;t++){
        if(bk[t] >= B){
            int pos = atomicAdd(&s_cnt,1);
            if(pos<256){
                unsigned int u = __float_as_uint(v[t]);
                u = (u & 0x80000000u) ? ~u : (u | 0x80000000u);
                cand[pos] = ((unsigned long long)u<<32) | (unsigned int)(~(base+t));
            }
        }
    }
    __syncthreads();
    int cnt = s_cnt;
    if(cnt<=256){
        if(tid==0){
            int sz = 32;
            while(sz < cnt) sz <<= 1;
            s_size = sz;
        }
        __syncthreads();
        int sz = s_size;
        if(tid<sz && tid>=cnt) cand[tid]=0ull;
        __syncthreads();
        for(int k=2;k<=sz;k<<=1){
            for(int j=k>>1;j>0;j>>=1){
                int ixj = tid ^ j;
                if(ixj > tid && ixj < sz && tid < sz){
                    bool up = ((tid & k) == 0);
                    unsigned long long a=cand[tid], c=cand[ixj];
                    if( (a > c) == up ){ cand[tid]=c; cand[ixj]=a; }
                }
                __syncthreads();
            }
        }
        if(tid<KNB)
            g_idx[((size_t)bq*NN+n)*KNB + tid] = (int)(~(unsigned int)cand[sz-1-tid]);
    } else {
        if(tid==0){
            if(FUSED3){
                int chosen[KNB];
                for(int j=0;j<KNB;j++){
                    float bvv=-FLT_MAX; int bii=0;
                    for(int i=0;i<NN;i++){
                        bool skip=false;
                        for(int q=0;q<j;q++) if(chosen[q]==i){ skip=true; break; }
                        if(skip) continue;
                        float a0=X3[i*3],a1=X3[i*3+1],a2=X3[i*3+2];
                        float ac=__fmaf_rn(X3[n*3],a0,0.f);
                        ac=__fmaf_rn(X3[n*3+1],a1,ac);
                        ac=__fmaf_rn(X3[n*3+2],a2,ac);
                        float vv=__fsub_rn(__fsub_rn(__fmul_rn(2.0f,ac),xxn),xxr[i]);
                        if(vv>bvv){ bvv=vv; bii=i; }
                    }
                    chosen[j]=bii;
                    g_idx[((size_t)bq*NN+n)*KNB + j]=bii;
                }
            } else {
                float* rw = g_dist + ((size_t)bq*NN + n)*NN;
                for(int j=0;j<KNB;j++){
                    float bvv=-FLT_MAX; int bii=0;
                    for(int i=0;i<NN;i++){ float vv=rw[i]; if(vv>bvv){bvv=vv;bii=i;} }
                    g_idx[((size_t)bq*NN+n)*KNB + j]=bii;
                    rw[bii]=-FLT_MAX;
                }
            }
        }
    }
}

__global__ void __launch_bounds__(256) k_topk(){
    int n = blockIdx.x, bq = blockIdx.y;
    const float* row = g_dist + ((size_t)bq*NN + n)*NN;
    int tid = threadIdx.x, lane = tid&31, w = tid>>5;
    float v[8];
    {
        const float4* r4 = (const float4*)(row + tid*8);
        float4 q0 = r4[0], q1 = r4[1];
        v[0]=q0.x; v[1]=q0.y; v[2]=q0.z; v[3]=q0.w;
        v[4]=q1.x; v[5]=q1.y; v[6]=q1.z; v[7]=q1.w;
    }
    topk_select<0>(v, tid, lane, w, n, bq, nullptr, 0.f, nullptr);
}

__global__ void __launch_bounds__(256) k_topk3(){
    int n = blockIdx.x, bq = blockIdx.y;
    const float* X3 = g_xT + (size_t)bq*NN*3;
    const float* xxr = g_xx + (size_t)bq*NN;
    int tid = threadIdx.x, lane = tid&31, w = tid>>5;
    float c0 = X3[n*3], c1 = X3[n*3+1], c2 = X3[n*3+2];
    float xxn = xxr[n];
    float f[24];
    {
        const float4* p4 = (const float4*)(X3 + tid*24);
        #pragma unroll
        for(int q=0;q<6;q++){
            float4 t = p4[q];
            f[q*4+0]=t.x; f[q*4+1]=t.y; f[q*4+2]=t.z; f[q*4+3]=t.w;
        }
    }
    float v[8];
    #pragma unroll
    for(int q=0;q<8;q++){
        float ac = __fmaf_rn(c0, f[q*3+0], 0.f);
        ac = __fmaf_rn(c1, f[q*3+1], ac);
        ac = __fmaf_rn(c2, f[q*3+2], ac);
        v[q] = __fsub_rn(__fsub_rn(__fmul_rn(2.0f, ac), xxn), xxr[tid*8+q]);
    }
    topk_select<1>(v, tid, lane, w, n, bq, X3, xxn, xxr);
}

__global__ void k_ec_stats(int O){
    int o = blockIdx.x, tid = threadIdx.x;
    double s=0.0, ss=0.0;
    for(int b=0;b<BB;b++){
        size_t base = ((size_t)b*O + o)*NN;
        for(int n=tid;n<NN;n+=256){ s += g_ksum[base+n]; ss += g_ksq[base+n]; }
    }
    __shared__ double rs[256], rq[256];
    rs[tid]=s; rq[tid]=ss; __syncthreads();
    for(int st=128;st;st>>=1){ if(tid<st){ rs[tid]+=rs[tid+st]; rq[tid]+=rq[tid+st]; } __syncthreads(); }
    if(tid==0){
        double cnt = (double)BB*NN*KNB;
        double mean = rs[0]/cnt;
        double var  = rq[0]/cnt - mean*mean;
        g_prm[2*o]   = (float)mean;
        g_prm[2*o+1] = (float)var;
    }
}

__global__ void __launch_bounds__(256) k_ec_apply2(int O, int c0, float* __restrict__ xTout,
                            const float* __restrict__ gw, const float* __restrict__ bw){
    int o0 = blockIdx.x*32;
    int n0base = blockIdx.y*256;
    int b = blockIdx.z;
    __shared__ float pmm[32], psd[32], pg[32], pb[32];
    __shared__ int   puse[32];
    __shared__ float tile[64][33];
    int tid = threadIdx.x;
    if(tid<32){
        int o = o0+tid;
        float m = g_prm[2*o], vv = g_prm[2*o+1];
        pmm[tid]=m; psd[tid]=__fsqrt_rn(__fadd_rn(vv, EPSB));
        pg[tid]=gw[o]; pb[tid]=bw[o];
        puse[tid] = (gw[o]>=0.f) ? 1 : 0;
    }
    __syncthreads();
    for(int s=0;s<4;s++){
        int n0 = n0base + s*64;
        #pragma unroll
        for(int e=tid; e<2048; e+=256){
            int ol=e>>6, nl=e&63;
            const float* src = puse[ol] ? g_kmax : g_kmin;
            float vsrc = src[((size_t)b*O + o0+ol)*NN + n0+nl];
            float y = __fadd_rn(__fmul_rn(__fdiv_rn(__fsub_rn(vsrc, pmm[ol]), psd[ol]), pg[ol]), pb[ol]);
            y = (y>=0.f) ? y : __fmul_rn(NEGS, y);
            g_xcat[((size_t)b*512 + c0 + o0+ol)*NN + n0+nl] = y;
            tile[nl][ol] = y;
        }
        __syncthreads();
        #pragma unroll
        for(int e=tid; e<2048; e+=256){
            int nl=e>>5, ol=e&31;
            xTout[((size_t)b*NN + n0+nl)*O + o0+ol] = tile[nl][ol];
        }
        __syncthreads();
    }
}

__global__ void k_conv_stats(const float* __restrict__ h, int O){
    int o = blockIdx.x, tid = threadIdx.x;
    double s=0.0, ss=0.0;
    for(int b=0;b<BB;b++){
        size_t base = ((size_t)b*O + o)*NN;
        for(int n=tid;n<NN;n+=256){ float v=h[base+n]; s += v; ss += (double)v*v; }
    }
    __shared__ double rs[256], rq[256];
    rs[tid]=s; rq[tid]=ss; __syncthreads();
    for(int st=128;st;st>>=1){ if(tid<st){ rs[tid]+=rs[tid+st]; rq[tid]+=rq[tid+st]; } __syncthreads(); }
    if(tid==0){
        double cnt = (double)BB*NN;
        double mean = rs[0]/cnt;
        double var  = rq[0]/cnt - mean*mean;
        g_prm[2*o]   = (float)mean;
        g_prm[2*o+1] = (float)var;
    }
}

__global__ void k_conv_apply(float* __restrict__ h, int O,
                             const float* __restrict__ gw, const float* __restrict__ bw){
    int o = blockIdx.x, b = blockIdx.y;
    float m = g_prm[2*o], vv = g_prm[2*o+1];
    float gg = gw[o], bb = bw[o];
    float sd = __fsqrt_rn(__fadd_rn(vv, EPSB));
    float* p = h + ((size_t)b*O + o)*NN;
    for(int n=threadIdx.x;n<NN;n+=blockDim.x){
        float y = __fadd_rn(__fmul_rn(__fdiv_rn(__fsub_rn(p[n], m), sd), gg), bb);
        p[n] = (y>=0.f) ? y : __fmul_rn(NEGS, y);
    }
}

__global__ void __launch_bounds__(256) k_h5stats(const float* __restrict__ gw,
                                                 const float* __restrict__ bw){
    int o = blockIdx.x, tid = threadIdx.x, lane = tid&31, w = tid>>5;
    double s=0.0, ss=0.0;
    float bmx[BB], bmn[BB];
    #pragma unroll
    for(int b=0;b<BB;b++){ bmx[b]=-FLT_MAX; bmn[b]=FLT_MAX; }
    for(int b=0;b<BB;b++){
        size_t base = ((size_t)b*1024 + o)*NN;
        for(int n=tid;n<NN;n+=256){
            float v = g_h5[base+n];
            s += v; ss += (double)v*v;
            bmx[b]=fmaxf(bmx[b],v); bmn[b]=fminf(bmn[b],v);
        }
    }
    __shared__ double rs[256], rq[256];
    rs[tid]=s; rq[tid]=ss; __syncthreads();
    for(int st=128;st;st>>=1){ if(tid<st){ rs[tid]+=rs[tid+st]; rq[tid]+=rq[tid+st]; } __syncthreads(); }
    __shared__ float sx[8][BB], sn[8][BB];
    #pragma unroll
    for(int b=0;b<BB;b++){
        float mx=bmx[b], mn=bmn[b];
        #pragma unroll
        for(int off=16;off;off>>=1){
            mx=fmaxf(mx,__shfl_xor_sync(0xffffffffu,mx,off));
            mn=fminf(mn,__shfl_xor_sync(0xffffffffu,mn,off));
        }
        if(lane==0){ sx[w][b]=mx; sn[w][b]=mn; }
    }
    __shared__ float smean, svar;
    __syncthreads();
    if(tid==0){
        double cnt = (double)BB*NN;
        double mean = rs[0]/cnt;
        double var  = rq[0]/cnt - mean*mean;
        smean = (float)mean; svar = (float)var;
    }
    __syncthreads();
    if(tid<BB){
        int b = tid;
        float mx=sx[0][b], mn=sn[0][b];
        #pragma unroll
        for(int q=1;q<8;q++){ mx=fmaxf(mx,sx[q][b]); mn=fminf(mn,sn[q][b]); }
        float gg = gw[o];
        float src = (gg>=0.f) ? mx : mn;
        float sd = __fsqrt_rn(__fadd_rn(svar, EPSB));
        float y = __fadd_rn(__fmul_rn(__fdiv_rn(__fsub_rn(src, smean), sd), gg), bw[o]);
        y = (y>=0.f) ? y : __fmul_rn(NEGS, y);
        g_glob[b*1088 + o] = y;
    }
}

__global__ void k_lf(const float* __restrict__ l, const float* __restrict__ W,
                     const float* __restrict__ gw, const float* __restrict__ bw){
    int tid = threadIdx.x;
    int o = tid & 63, b = tid >> 6;
    __shared__ float hs[8][64];
    __shared__ float pm[64], pv[64];
    float s = 0.f;
    #pragma unroll
    for(int c=0;c<16;c++) s = __fmaf_rn(W[o*16 + c], l[b*16 + c], s);
    hs[b][o] = s;
    __syncthreads();
    if(tid < 64){
        float m = 0.f;
        #pragma unroll
        for(int q=0;q<8;q++) m = __fadd_rn(m, hs[q][tid]);
        m = __fdiv_rn(m, 8.f);
        float v = 0.f;
        #pragma unroll
        for(int q=0;q<8;q++){ float d = __fsub_rn(hs[q][tid], m); v = __fmaf_rn(d, d, v); }
        v = __fdiv_rn(v, 8.f);
        pm[tid] = m; pv[tid] = v;
    }
    __syncthreads();
    float sd = __fsqrt_rn(__fadd_rn(pv[o], EPSB));
    float y = __fadd_rn(__fmul_rn(__fdiv_rn(__fsub_rn(hs[b][o], pm[o]), sd), gw[o]), bw[o]);
    y = (y>=0.f) ? y : __fmul_rn(NEGS, y);
    g_glob[b*1088 + 1024 + o] = y;
}

__global__ void k_bias207(const float* __restrict__ W207){
    int b = blockIdx.x;
    __shared__ float gl[1088];
    for(int i=threadIdx.x;i<1088;i+=256) gl[i] = g_glob[b*1088 + i];
    __syncthreads();
    int o = threadIdx.x;
    float s = 0.f;
    for(int c=0;c<1088;c++) s = __fmaf_rn(W207[(size_t)o*1600 + c], gl[c], s);
    g_b207[b*256 + o] = s;
}

// ------------------------- launcher -------------------------
extern "C" void kernel_launch(void* const* d_in, const int* in_sizes, int n_in,
                              void* d_out, int out_size){
    (void)in_sizes; (void)n_in; (void)out_size;
    const float* x    = (const float*)d_in[0];
    const float* l    = (const float*)d_in[1];
    const float* Wec[4] = {(const float*)d_in[2],(const float*)d_in[5],(const float*)d_in[8],(const float*)d_in[11]};
    const float* gec[4] = {(const float*)d_in[3],(const float*)d_in[6],(const float*)d_in[9],(const float*)d_in[12]};
    const float* bec[4] = {(const float*)d_in[4],(const float*)d_in[7],(const float*)d_in[10],(const float*)d_in[13]};
    const float* W5   = (const float*)d_in[14]; const float* g5v  = (const float*)d_in[15]; const float* b5v  = (const float*)d_in[16];
    const float* W206 = (const float*)d_in[17]; const float* g206 = (const float*)d_in[18]; const float* b206 = (const float*)d_in[19];
    const float* W207 = (const float*)d_in[20]; const float* g207 = (const float*)d_in[21]; const float* b207 = (const float*)d_in[22];
    const float* W208 = (const float*)d_in[23]; const float* g208 = (const float*)d_in[24]; const float* b208 = (const float*)d_in[25];
    const float* W209 = (const float*)d_in[26]; const float* g209 = (const float*)d_in[27]; const float* b209 = (const float*)d_in[28];
    const float* W2010= (const float*)d_in[29];

    float *xT,*xxp,*xcat,*h5,*hb1,*hb2,*hb3,*b207p,*basep,*Wdp;
    int *idxp;
    cudaGetSymbolAddress((void**)&xT,   g_xT);
    cudaGetSymbolAddress((void**)&xxp,  g_xx);
    cudaGetSymbolAddress((void**)&idxp, g_idx);
    cudaGetSymbolAddress((void**)&xcat, g_xcat);
    cudaGetSymbolAddress((void**)&h5,   g_h5);
    cudaGetSymbolAddress((void**)&hb1,  g_hb1);
    cudaGetSymbolAddress((void**)&hb2,  g_hb2);
    cudaGetSymbolAddress((void**)&hb3,  g_hb3);
    cudaGetSymbolAddress((void**)&b207p,g_b207);
    cudaGetSymbolAddress((void**)&basep,g_base);
    cudaGetSymbolAddress((void**)&Wdp,  g_Wd);

    const int Cin[4] = {3,64,64,128};
    const int Oo [4] = {64,64,128,256};
    const int c0 [4] = {0,64,128,256};

    k_tin<<<(BB*NN*3 + 255)/256, 256>>>(x);

    for(int li=0; li<4; li++){
        int C = Cin[li], O = Oo[li];
        k_xx<<<(BB*NN + 255)/256, 256>>>(C);
        if(li==0){
            k_topk3<<<dim3(NN, BB), 256>>>();
        } else {
            k_dgemm<<<dim3(NN/128, NN/128, BB), 256>>>(C, xT, xxp);
            k_topk<<<dim3(NN, BB), 256>>>();
        }
        if(li==0){
            k_egemm_t<3,64,3><<<dim3(NN/8, 1, BB), 256>>>(64, Wec[0], xT, idxp);
        } else {
            // split: base = (W_b - W_a) @ ctr, then h = W_a @ nbr + base (3xTF32)
            k_wdiff<<<(O*C + 255)/256, 256>>>(Wec[li], O, C);
            k_gemm<false,0><<<dim3(NN/128, (O+127)/128, BB), 256>>>(
                O, NN, C, Wdp, C, 0, xT, C, (size_t)NN*C, basep, (size_t)O*NN, nullptr);
            if(li==1)      k_egemm_tc<64, 2,4><<<dim3(NN/8, 1, BB), 256>>>(64,  Wec[1], xT, idxp);
            else if(li==2) k_egemm_tc<64, 4,2><<<dim3(NN/4, 1, BB), 256>>>(128, Wec[2], xT, idxp);
            else           k_egemm_tc<128,4,2><<<dim3(NN/4, 2, BB), 256>>>(256, Wec[3], xT, idxp);
        }
        k_ec_stats<<<O, 256>>>(O);
        k_ec_apply2<<<dim3(O/32, NN/256, BB), 256>>>(O, c0[li], xT, gec[li], bec[li]);
    }

    // ---- continuous tail: 3xTF32 tensor cores (fp32-accurate) ----
    k_tgemm<0><<<dim3(NN/64, 1024/128, BB), 256>>>(
        1024, 512, W5, 512, xcat, (size_t)512*NN, NN, h5, (size_t)1024*NN, nullptr);
    k_h5stats<<<1024, 256>>>(g5v, b5v);
    k_lf<<<1, 512>>>(l, W206, g206, b206);
    k_bias207<<<BB, 256>>>(W207);
    k_tgemm<2><<<dim3(NN/64, 2, BB), 256>>>(
        256, 512, W207 + 1088, 1600, xcat, (size_t)512*NN, NN, hb1, (size_t)256*NN, b207p);
    k_conv_stats<<<256, 256>>>(hb1, 256);
    k_conv_apply<<<dim3(256, BB), 256>>>(hb1, 256, g207, b207);
    k_tgemm<0><<<dim3(NN/64, 2, BB), 256>>>(
        256, 256, W208, 256, hb1, (size_t)256*NN, NN, hb2, (size_t)256*NN, nullptr);
    k_conv_stats<<<256, 256>>>(hb2, 256);
    k_conv_apply<<<dim3(256, BB), 256>>>(hb2, 256, g208, b208);
    k_tgemm<0><<<dim3(NN/64, 1, BB), 256>>>(
        128, 256, W209, 256, hb2, (size_t)256*NN, NN, hb3, (size_t)128*NN, nullptr);
    k_conv_stats<<<128, 256>>>(hb3, 128);
    k_conv_apply<<<dim3(128, BB), 256>>>(hb3, 128, g209, b209);
    k_tgemm<0><<<dim3(NN/64, 1, BB), 256>>>(
        50, 128, W2010, 128, hb3, (size_t)128*NN, NN, (float*)d_out, (size_t)50*NN, nullptr);
}

// round 17
// speedup vs baseline: 1.1467x; 1.1467x over previous
#include <cuda_runtime.h>
#include <cstdlib>
#include <cstdint>
#include <cfloat>

#define BB 8
#define NN 2048
#define KNB 20
#define NEGS 0.2f
#define EPSB 1e-5f

__attribute__((constructor)) static void _eager_load(){ setenv("CUDA_MODULE_LOADING","EAGER",0); }

// ------------------------- scratch (device globals) -------------------------
__device__ float g_xT  [(size_t)BB*NN*256];
__device__ float g_xx  [BB*NN];
__device__ float g_dist[(size_t)BB*NN*NN];
__device__ int   g_idx [(size_t)BB*NN*KNB];
__device__ float g_kmax[(size_t)BB*256*NN];
__device__ float g_kmin[(size_t)BB*256*NN];
__device__ float g_ksum[(size_t)BB*256*NN];
__device__ float g_ksq [(size_t)BB*256*NN];
__device__ float g_base[(size_t)BB*256*NN];   // (W_b - W_a) @ ctr
__device__ float g_Wd  [256*128];             // W[:,C:2C] - W[:,:C]
__device__ float g_xcat[(size_t)BB*512*NN];
__device__ float g_h5  [(size_t)BB*1024*NN];
__device__ float g_hb1 [(size_t)BB*256*NN];
__device__ float g_hb2 [(size_t)BB*256*NN];
__device__ float g_hb3 [(size_t)BB*128*NN];
__device__ float g_glob[BB*1088];
__device__ float g_b207[BB*256];
__device__ float g_prm [2048];

// ------------------------- packed fp32x2 FMA (sm_103a) ----------------------
// Lane-wise fma.rn => bit-identical to scalar __fmaf_rn chains.
__device__ __forceinline__ unsigned long long pk2(float lo, float hi){
    unsigned long long r; asm("mov.b64 %0, {%1,%2};" : "=l"(r) : "f"(lo), "f"(hi)); return r;
}
__device__ __forceinline__ void upk2(unsigned long long v, float &lo, float &hi){
    asm("mov.b64 {%0,%1}, %2;" : "=f"(lo), "=f"(hi) : "l"(v));
}
__device__ __forceinline__ void fma2(unsigned long long &d, unsigned long long a, unsigned long long b){
    asm("fma.rn.f32x2 %0, %1, %2, %0;" : "+l"(d) : "l"(a), "l"(b));
}

// ------------------------- TF32 helpers -------------------------
__device__ __forceinline__ uint32_t f2tf32(float x){
    uint32_t u; asm("cvt.rna.tf32.f32 %0, %1;" : "=r"(u) : "f"(x)); return u;
}
__device__ __forceinline__ void mma_tf32(float* d, const uint32_t* a, const uint32_t* b){
    asm volatile("mma.sync.aligned.m16n8k8.row.col.f32.tf32.tf32.f32 "
        "{%0,%1,%2,%3}, {%4,%5,%6,%7}, {%8,%9}, {%0,%1,%2,%3};"
        : "+f"(d[0]),"+f"(d[1]),"+f"(d[2]),"+f"(d[3])
        : "r"(a[0]),"r"(a[1]),"r"(a[2]),"r"(a[3]), "r"(b[0]),"r"(b[1]));
}

// ------------------------- generic fp32 GEMM (pipelined, f32x2 core) --------
template<bool BT, int MODE>
__global__ void __launch_bounds__(256,2) k_gemm(
    int M, int Ncol, int Kd,
    const float* __restrict__ A, int lda, size_t asb,
    const float* __restrict__ Bp, int ldb, size_t bsb,
    float* __restrict__ Cp, size_t csb,
    const float* __restrict__ e0)
{
    const int BM=128, BN=128, BK=16;
    __shared__ float As[2][BK][BM+4];
    __shared__ float Bs[2][BK][BN+4];
    int b  = blockIdx.z;
    int m0 = blockIdx.y*BM, n0 = blockIdx.x*BN;
    A  += (size_t)b*asb;
    Bp += (size_t)b*bsb;
    Cp += (size_t)b*csb;
    int tid = threadIdx.x;
    int tx = tid%16, ty = tid/16;

    unsigned long long acc2[8][4];
    #pragma unroll
    for(int i=0;i<8;i++)
        #pragma unroll
        for(int j=0;j<4;j++) acc2[i][j]=0ull;

    float ra[8], rb[8];

    auto fetchA = [&](int k0){
        #pragma unroll
        for(int i=0;i<8;i++){
            int e = tid + 256*i;
            int kk=e%BK, mm=e/BK;
            int gm=m0+mm, gk=k0+kk;
            ra[i] = (gm<M && gk<Kd) ? A[(size_t)gm*lda+gk] : 0.f;
        }
    };
    auto fetchB = [&](int k0){
        if(!BT){
            #pragma unroll
            for(int i=0;i<8;i++){
                int e = tid + 256*i;
                int kk=e%BK, nn=e/BK;
                int gn=n0+nn, gk=k0+kk;
                rb[i] = (gn<Ncol && gk<Kd) ? Bp[(size_t)gn*ldb+gk] : 0.f;
            }
        } else {
            #pragma unroll
            for(int i=0;i<8;i++){
                int e = tid + 256*i;
                int nn=e%BN, kk=e/BN;
                int gn=n0+nn, gk=k0+kk;
                rb[i] = (gn<Ncol && gk<Kd) ? Bp[(size_t)gk*ldb+gn] : 0.f;
            }
        }
    };
    auto store = [&](int buf){
        #pragma unroll
        for(int i=0;i<8;i++){
            int e = tid + 256*i;
            As[buf][e%BK][e/BK] = ra[i];
        }
        if(!BT){
            #pragma unroll
            for(int i=0;i<8;i++){
                int e = tid + 256*i;
                Bs[buf][e%BK][e/BK] = rb[i];
            }
        } else {
            #pragma unroll
            for(int i=0;i<8;i++){
                int e = tid + 256*i;
                Bs[buf][e/BN][e%BN] = rb[i];
            }
        }
    };

    int nk = (Kd + BK - 1)/BK;
    fetchA(0); fetchB(0);
    store(0);
    __syncthreads();

    for(int t=0;t<nk;t++){
        int cur = t&1;
        if(t+1<nk){ fetchA((t+1)*BK); fetchB((t+1)*BK); }
        #pragma unroll
        for(int kk=0;kk<BK;kk++){
            float a8[8], b8[8];
            #pragma unroll
            for(int i=0;i<8;i++) a8[i]=As[cur][kk][ty*8+i];
            #pragma unroll
            for(int j=0;j<8;j++) b8[j]=Bs[cur][kk][tx*8+j];
            unsigned long long bp[4];
            #pragma unroll
            for(int j=0;j<4;j++) bp[j]=pk2(b8[2*j], b8[2*j+1]);
            #pragma unroll
            for(int i=0;i<8;i++){
                unsigned long long a2 = pk2(a8[i], a8[i]);
                #pragma unroll
                for(int j=0;j<4;j++) fma2(acc2[i][j], a2, bp[j]);
            }
        }
        if(t+1<nk){
            __syncthreads();
            store(1-cur);
            __syncthreads();
        }
    }

    #pragma unroll
    for(int i=0;i<8;i++){
        int gm = m0+ty*8+i;
        if(gm>=M) continue;
        float accr[8];
        #pragma unroll
        for(int j=0;j<4;j++) upk2(acc2[i][j], accr[2*j], accr[2*j+1]);
        #pragma unroll
        for(int j=0;j<8;j++){
            int gn = n0+tx*8+j;
            if(gn>=Ncol) continue;
            float v = accr[j];
            if(MODE==2) v = __fadd_rn(v, e0[(size_t)b*M+gm]);
            Cp[(size_t)gm*Ncol + gn] = v;
        }
    }
}

// ------------------- 3xTF32 tensor-core tail GEMM ---------------------------
template<int MODE>
__global__ void __launch_bounds__(256,3) k_tgemm(
    int M, int Kd,
    const float* __restrict__ A, int lda,
    const float* __restrict__ Bp, size_t bsb, int ldb,
    float* __restrict__ Cp, size_t csb,
    const float* __restrict__ e0)
{
    const int BM=128, BN=64, BK=16;
    __shared__ float Ah[BM][20], Al[BM][20];
    __shared__ float Bh[BK][72], Bl[BK][72];
    int b  = blockIdx.z;
    int m0 = blockIdx.y*BM, n0 = blockIdx.x*BN;
    Bp += (size_t)b*bsb;
    Cp += (size_t)b*csb;
    int tid = threadIdx.x;
    int lane = tid&31, warp = tid>>5;
    int wm = warp>>1, wn = warp&1;
    int gID = lane>>2, tig = lane&3;

    float acc[2][4][4];
    #pragma unroll
    for(int i=0;i<2;i++)
        #pragma unroll
        for(int j=0;j<4;j++)
            #pragma unroll
            for(int q=0;q<4;q++) acc[i][j][q]=0.f;

    int nk = Kd/BK;
    for(int t=0;t<nk;t++){
        int k0 = t*BK;
        #pragma unroll
        for(int i=0;i<8;i++){
            int e = tid + 256*i;
            int k = e&15, m = e>>4;
            int gm = m0+m;
            float x = (gm<M) ? A[(size_t)gm*lda + k0+k] : 0.f;
            float hi = __uint_as_float(f2tf32(x));
            float lo = __uint_as_float(f2tf32(__fsub_rn(x, hi)));
            Ah[m][k] = hi; Al[m][k] = lo;
        }
        #pragma unroll
        for(int i=0;i<4;i++){
            int e = tid + 256*i;
            int n = e&63, k = e>>6;
            float x = Bp[(size_t)(k0+k)*ldb + n0+n];
            float hi = __uint_as_float(f2tf32(x));
            float lo = __uint_as_float(f2tf32(__fsub_rn(x, hi)));
            Bh[k][n] = hi; Bl[k][n] = lo;
        }
        __syncthreads();
        #pragma unroll
        for(int kk=0;kk<BK;kk+=8){
            uint32_t afh[2][4], afl[2][4], bfh[4][2], bfl[4][2];
            #pragma unroll
            for(int mt=0;mt<2;mt++){
                int row = wm*32 + mt*16;
                afh[mt][0] = __float_as_uint(Ah[row+gID  ][kk+tig  ]);
                afh[mt][1] = __float_as_uint(Ah[row+gID+8][kk+tig  ]);
                afh[mt][2] = __float_as_uint(Ah[row+gID  ][kk+tig+4]);
                afh[mt][3] = __float_as_uint(Ah[row+gID+8][kk+tig+4]);
                afl[mt][0] = __float_as_uint(Al[row+gID  ][kk+tig  ]);
                afl[mt][1] = __float_as_uint(Al[row+gID+8][kk+tig  ]);
                afl[mt][2] = __float_as_uint(Al[row+gID  ][kk+tig+4]);
                afl[mt][3] = __float_as_uint(Al[row+gID+8][kk+tig+4]);
            }
            #pragma unroll
            for(int nt=0;nt<4;nt++){
                int col = wn*32 + nt*8 + gID;
                bfh[nt][0] = __float_as_uint(Bh[kk+tig  ][col]);
                bfh[nt][1] = __float_as_uint(Bh[kk+tig+4][col]);
                bfl[nt][0] = __float_as_uint(Bl[kk+tig  ][col]);
                bfl[nt][1] = __float_as_uint(Bl[kk+tig+4][col]);
            }
            #pragma unroll
            for(int mt=0;mt<2;mt++)
                #pragma unroll
                for(int nt=0;nt<4;nt++){
                    mma_tf32(acc[mt][nt], afl[mt], bfh[nt]);
                    mma_tf32(acc[mt][nt], afh[mt], bfl[nt]);
                    mma_tf32(acc[mt][nt], afh[mt], bfh[nt]);
                }
        }
        __syncthreads();
    }

    #pragma unroll
    for(int mt=0;mt<2;mt++){
        int r0 = m0 + wm*32 + mt*16 + gID;
        int r1 = r0 + 8;
        #pragma unroll
        for(int nt=0;nt<4;nt++){
            int c0 = n0 + wn*32 + nt*8 + tig*2;
            float v0=acc[mt][nt][0], v1=acc[mt][nt][1], v2=acc[mt][nt][2], v3=acc[mt][nt][3];
            if(MODE==2){
                if(r0<M){ float e=e0[(size_t)b*M+r0]; v0=__fadd_rn(v0,e); v1=__fadd_rn(v1,e); }
                if(r1<M){ float e=e0[(size_t)b*M+r1]; v2=__fadd_rn(v2,e); v3=__fadd_rn(v3,e); }
            }
            if(r0<M){ Cp[(size_t)r0*NN + c0] = v0; Cp[(size_t)r0*NN + c0+1] = v1; }
            if(r1<M){ Cp[(size_t)r1*NN + c0] = v2; Cp[(size_t)r1*NN + c0+1] = v3; }
        }
    }
}

// -------- symmetric dist GEMM (layers 2-4, f32x2 core) ----------------------
__global__ void __launch_bounds__(256,2) k_dgemm(
    int Kd, const float* __restrict__ Xp, const float* __restrict__ e0)
{
    const int BK=16;
    if(blockIdx.x < blockIdx.y) return;
    __shared__ float pool[8448];
    #define ASM(buf,kk,mm) pool[(buf)*2112 + (kk)*132 + (mm)]
    #define BSM(buf,kk,nn) pool[4224 + (buf)*2112 + (kk)*132 + (nn)]
    int b  = blockIdx.z;
    int m0 = blockIdx.y*128, n0 = blockIdx.x*128;
    const float* A = Xp + (size_t)b*NN*Kd;
    float* Cp = g_dist + (size_t)b*NN*NN;
    const float* xxr = e0 + (size_t)b*NN;
    int tid = threadIdx.x;
    int tx = tid%16, ty = tid/16;

    unsigned long long acc2[8][4];
    #pragma unroll
    for(int i=0;i<8;i++)
        #pragma unroll
        for(int j=0;j<4;j++) acc2[i][j]=0ull;

    float ra[8], rb[8];
    auto fetchA = [&](int k0){
        #pragma unroll
        for(int i=0;i<8;i++){
            int e = tid + 256*i;
            int kk=e&15, mm=e>>4;
            int gk=k0+kk;
            ra[i] = (gk<Kd) ? A[(size_t)(m0+mm)*Kd+gk] : 0.f;
        }
    };
    auto fetchB = [&](int k0){
        #pragma unroll
        for(int i=0;i<8;i++){
            int e = tid + 256*i;
            int kk=e&15, nn=e>>4;
            int gk=k0+kk;
            rb[i] = (gk<Kd) ? A[(size_t)(n0+nn)*Kd+gk] : 0.f;
        }
    };
    auto store = [&](int buf){
        #pragma unroll
        for(int i=0;i<8;i++){
            int e = tid + 256*i;
            ASM(buf, e&15, e>>4) = ra[i];
        }
        #pragma unroll
        for(int i=0;i<8;i++){
            int e = tid + 256*i;
            BSM(buf, e&15, e>>4) = rb[i];
        }
    };

    int nk = (Kd + BK - 1)/BK;
    fetchA(0); fetchB(0);
    store(0);
    __syncthreads();
    for(int t=0;t<nk;t++){
        int cur = t&1;
        if(t+1<nk){ fetchA((t+1)*BK); fetchB((t+1)*BK); }
        #pragma unroll
        for(int kk=0;kk<BK;kk++){
            float a8[8], b8[8];
            #pragma unroll
            for(int i=0;i<8;i++) a8[i]=ASM(cur,kk,ty*8+i);
            #pragma unroll
            for(int j=0;j<8;j++) b8[j]=BSM(cur,kk,tx*8+j);
            unsigned long long bp[4];
            #pragma unroll
            for(int j=0;j<4;j++) bp[j]=pk2(b8[2*j], b8[2*j+1]);
            #pragma unroll
            for(int i=0;i<8;i++){
                unsigned long long a2 = pk2(a8[i], a8[i]);
                #pragma unroll
                for(int j=0;j<4;j++) fma2(acc2[i][j], a2, bp[j]);
            }
        }
        if(t+1<nk){
            __syncthreads();
            store(1-cur);
            __syncthreads();
        }
    }

    float acc[8][8];
    #pragma unroll
    for(int i=0;i<8;i++)
        #pragma unroll
        for(int j=0;j<4;j++) upk2(acc2[i][j], acc[i][2*j], acc[i][2*j+1]);

    #pragma unroll
    for(int i=0;i<8;i++){
        int gm = m0+ty*8+i;
        float xm = xxr[gm];
        #pragma unroll
        for(int j=0;j<8;j++){
            int gn = n0+tx*8+j;
            float v = __fsub_rn(__fsub_rn(__fmul_rn(2.0f, acc[i][j]), xm), xxr[gn]);
            acc[i][j] = v;
            Cp[(size_t)gm*NN + gn] = v;
        }
    }
    if(blockIdx.x > blockIdx.y){
        for(int c=0;c<4;c++){
            __syncthreads();
            if((tx>>2)==c){
                int tl = tx&3;
                #pragma unroll
                for(int i=0;i<8;i++)
                    #pragma unroll
                    for(int j=0;j<8;j++)
                        pool[(tl*8+j)*132 + ty*8+i] = acc[i][j];
            }
            __syncthreads();
            #pragma unroll
            for(int q=0;q<16;q++){
                int e = tid + 256*q;
                int rr=e>>7, cc=e&127;
                Cp[(size_t)(n0+c*32+rr)*NN + m0+cc] = pool[rr*132+cc];
            }
        }
    }
    #undef ASM
    #undef BSM
}

// ------- L1 exact fused edge-conv GEMM + k-reduce (full 2C path, fp32) ------
template<int C, int BM, int MAXB>
__global__ void __launch_bounds__(256,MAXB) k_egemm_t(
    int M,
    const float* __restrict__ A,
    const float* __restrict__ xTp,
    const int*   __restrict__ idxp)
{
    const int BN=160, BK=16;
    const int Kd = 2*C;
    const int NK = (Kd + BK - 1)/BK;
    const int TM = BM/16;
    const int NA = BM*BK/256;
    __shared__ float As[2][BK][BM+4];
    __shared__ float Bs[2][BK][BN+4];
    __shared__ int   s_moff[BN];
    __shared__ int   s_poff[BN];
    int b  = blockIdx.z;
    int m0 = blockIdx.y*BM;
    int p0 = blockIdx.x*8;
    xTp  += (size_t)b*NN*C;
    idxp += (size_t)b*NN*KNB;
    int tid = threadIdx.x;
    int tx = tid%16, ty = tid/16;

    if(tid < BN){
        int pt = tid/KNB;
        int kq = tid - pt*KNB;
        s_poff[tid] = (p0+pt)*C;
        s_moff[tid] = idxp[(size_t)(p0+pt)*KNB + kq]*C;
    }
    __syncthreads();

    float acc[TM][10];
    #pragma unroll
    for(int i=0;i<TM;i++)
        #pragma unroll
        for(int j=0;j<10;j++) acc[i][j]=0.f;

    float ra[NA], rb[10];
    int kkme = tid & 15;

    auto fetchA = [&](int k0){
        #pragma unroll
        for(int i=0;i<NA;i++){
            int e = tid + 256*i;
            int kk=e&15, mm=e>>4;
            int gk=k0+kk;
            ra[i] = (gk<Kd) ? A[(size_t)(m0+mm)*Kd+gk] : 0.f;
        }
    };
    auto fetchB = [&](int k0){
        int gk = k0 + kkme;
        #pragma unroll
        for(int i=0;i<10;i++){
            int nn = (tid>>4) + 16*i;
            float val = 0.f;
            if(gk < Kd){
                int cc = (gk<C) ? gk : gk-C;
                float ctr = xTp[s_poff[nn] + cc];
                if(gk<C) val = __fsub_rn(xTp[s_moff[nn] + cc], ctr);
                else     val = ctr;
            }
            rb[i] = val;
        }
    };
    auto store = [&](int buf){
        #pragma unroll
        for(int i=0;i<NA;i++){
            int e = tid + 256*i;
            As[buf][e&15][e>>4] = ra[i];
        }
        #pragma unroll
        for(int i=0;i<10;i++){
            int nn = (tid>>4) + 16*i;
            Bs[buf][kkme][nn] = rb[i];
        }
    };

    fetchA(0); fetchB(0);
    store(0);
    __syncthreads();

    #pragma unroll 1
    for(int t=0;t<NK;t++){
        int cur = t&1;
        if(t+1<NK){ fetchA((t+1)*BK); fetchB((t+1)*BK); }
        #pragma unroll
        for(int kk=0;kk<BK;kk++){
            float am[TM], b10[10];
            #pragma unroll
            for(int i=0;i<TM;i++) am[i]=As[cur][kk][ty*TM+i];
            #pragma unroll
            for(int j=0;j<10;j++) b10[j]=Bs[cur][kk][tx*10+j];
            #pragma unroll
            for(int i=0;i<TM;i++)
                #pragma unroll
                for(int j=0;j<10;j++) acc[i][j] = __fmaf_rn(am[i], b10[j], acc[i][j]);
        }
        if(t+1<NK){
            __syncthreads();
            store(1-cur);
            __syncthreads();
        }
    }

    int O = M;
    #pragma unroll
    for(int i=0;i<TM;i++){
        float mx=-FLT_MAX, mn=FLT_MAX, sm=0.f, sq=0.f;
        #pragma unroll
        for(int j=0;j<10;j++){
            float h = acc[i][j];
            mx = fmaxf(mx,h); mn = fminf(mn,h);
            sm = __fadd_rn(sm,h); sq = __fmaf_rn(h,h,sq);
        }
        #pragma unroll
        for(int j=0;j<10;j++){
            float h = __shfl_xor_sync(0xffffffffu, acc[i][j], 1);
            mx = fmaxf(mx,h); mn = fminf(mn,h);
            sm = __fadd_rn(sm,h); sq = __fmaf_rn(h,h,sq);
        }
        int gm = m0 + ty*TM + i;
        if((tx&1)==0){
            int point = p0 + (tx>>1);
            size_t base = ((size_t)b*O + gm)*NN + point;
            g_kmax[base]=mx; g_kmin[base]=mn; g_ksum[base]=sm; g_ksq[base]=sq;
        }
    }
}

// ------- SPLIT edge-conv GEMM (layers 2-4, f32x2 core) ----------------------
template<int C, int BM, int MAXB>
__global__ void __launch_bounds__(256,MAXB) k_egemm_s(
    int M,
    const float* __restrict__ A,
    const float* __restrict__ xTp,
    const int*   __restrict__ idxp)
{
    const int BN=160, BK=16;
    const int NK = C/BK;
    const int TM = BM/16;
    const int NA = BM*BK/256;
    __shared__ float As[2][BK][BM+4];
    __shared__ float Bs[2][BK][BN+4];
    __shared__ int   s_moff[BN];
    int b  = blockIdx.z;
    int m0 = blockIdx.y*BM;
    int p0 = blockIdx.x*8;
    xTp  += (size_t)b*NN*C;
    idxp += (size_t)b*NN*KNB;
    int tid = threadIdx.x;
    int tx = tid%16, ty = tid/16;

    if(tid < BN){
        int pt = tid/KNB;
        int kq = tid - pt*KNB;
        s_moff[tid] = idxp[(size_t)(p0+pt)*KNB + kq]*C;
    }
    __syncthreads();

    unsigned long long acc2[TM][5];
    #pragma unroll
    for(int i=0;i<TM;i++)
        #pragma unroll
        for(int j=0;j<5;j++) acc2[i][j]=0ull;

    float ra[NA], rb[10];
    int kkme = tid & 15;

    auto fetchA = [&](int k0){
        #pragma unroll
        for(int i=0;i<NA;i++){
            int e = tid + 256*i;
            int kk=e&15;
            ra[i] = A[(size_t)(m0+(e>>4))*(2*C) + k0+kk];
        }
    };
    auto fetchB = [&](int k0){
        int cc = k0 + kkme;
        #pragma unroll
        for(int i=0;i<10;i++){
            int nn = (tid>>4) + 16*i;
            rb[i] = xTp[s_moff[nn] + cc];
        }
    };
    auto store = [&](int buf){
        #pragma unroll
        for(int i=0;i<NA;i++){
            int e = tid + 256*i;
            As[buf][e&15][e>>4] = ra[i];
        }
        #pragma unroll
        for(int i=0;i<10;i++){
            int nn = (tid>>4) + 16*i;
            Bs[buf][kkme][nn] = rb[i];
        }
    };

    fetchA(0); fetchB(0);
    store(0);
    __syncthreads();

    #pragma unroll 1
    for(int t=0;t<NK;t++){
        int cur = t&1;
        if(t+1<NK){ fetchA((t+1)*BK); fetchB((t+1)*BK); }
        #pragma unroll
        for(int kk=0;kk<BK;kk++){
            float am[TM], b10[10];
            #pragma unroll
            for(int i=0;i<TM;i++) am[i]=As[cur][kk][ty*TM+i];
            #pragma unroll
            for(int j=0;j<10;j++) b10[j]=Bs[cur][kk][tx*10+j];
            unsigned long long bp[5];
            #pragma unroll
            for(int j=0;j<5;j++) bp[j]=pk2(b10[2*j], b10[2*j+1]);
            #pragma unroll
            for(int i=0;i<TM;i++){
                unsigned long long a2 = pk2(am[i], am[i]);
                #pragma unroll
                for(int j=0;j<5;j++) fma2(acc2[i][j], a2, bp[j]);
            }
        }
        if(t+1<NK){
            __syncthreads();
            store(1-cur);
            __syncthreads();
        }
    }

    int O = M;
    int point = p0 + (tx>>1);
    #pragma unroll
    for(int i=0;i<TM;i++){
        float accr[10];
        #pragma unroll
        for(int j=0;j<5;j++) upk2(acc2[i][j], accr[2*j], accr[2*j+1]);
        int gm = m0 + ty*TM + i;
        float bsv = g_base[((size_t)b*O + gm)*NN + point];
        float mx=-FLT_MAX, mn=FLT_MAX, sm=0.f, sq=0.f;
        #pragma unroll
        for(int j=0;j<10;j++){
            float h = __fadd_rn(accr[j], bsv);
            mx = fmaxf(mx,h); mn = fminf(mn,h);
            sm = __fadd_rn(sm,h); sq = __fmaf_rn(h,h,sq);
        }
        #pragma unroll
        for(int j=0;j<10;j++){
            float h = __fadd_rn(__shfl_xor_sync(0xffffffffu, accr[j], 1), bsv);
            mx = fmaxf(mx,h); mn = fminf(mn,h);
            sm = __fadd_rn(sm,h); sq = __fmaf_rn(h,h,sq);
        }
        if((tx&1)==0){
            size_t base = ((size_t)b*O + gm)*NN + point;
            g_kmax[base]=mx; g_kmin[base]=mn; g_ksum[base]=sm; g_ksq[base]=sq;
        }
    }
}

// ------------------------- small kernels -------------------------

__global__ void k_tin(const float* __restrict__ x){
    int i = blockIdx.x*blockDim.x + threadIdx.x;
    if(i >= BB*NN*3) return;
    int c = i%3; int n = (i/3)%NN; int b = i/(3*NN);
    g_xT[i] = x[((size_t)b*3 + c)*NN + n];
}

__global__ void k_xx(int C){
    int p = blockIdx.x*blockDim.x + threadIdx.x;
    if(p >= BB*NN) return;
    const float* v = g_xT + (size_t)p*C;
    float s = 0.f;
    for(int c=0;c<C;c++) s = __fadd_rn(s, __fmul_rn(v[c], v[c]));
    g_xx[p] = s;
}

__global__ void k_wdiff(const float* __restrict__ W, int O, int C){
    int i = blockIdx.x*blockDim.x + threadIdx.x;
    if(i >= O*C) return;
    int o = i/C, c = i%C;
    g_Wd[i] = __fsub_rn(W[(size_t)o*2*C + C + c], W[(size_t)o*2*C + c]);
}

// shared top-k selection body (given v[8] per thread).
template<int FUSED3>
__device__ __forceinline__ void topk_select(
    float* v, int tid, int lane, int w, int n, int bq,
    const float* __restrict__ X3, float xxn, const float* __restrict__ xxr)
{
    __shared__ float swmx[8], swmn[8];
    __shared__ int hist8[8][256];
    __shared__ int hist[256];
    __shared__ unsigned long long cand[256];
    __shared__ int s_cnt, s_B, s_size;
    __shared__ float s_lo, s_hi;
    int base = tid*8;

    float mx=v[0], mn=v[0];
    #pragma unroll
    for(int t=1;t<8;t++){ mx=fmaxf(mx,v[t]); mn=fminf(mn,v[t]); }
    #pragma unroll
    for(int o=16;o;o>>=1){
        mx=fmaxf(mx,__shfl_xor_sync(0xffffffffu,mx,o));
        mn=fminf(mn,__shfl_xor_sync(0xffffffffu,mn,o));
    }
    if(lane==0){ swmx[w]=mx; swmn[w]=mn; }
    #pragma unroll
    for(int q=0;q<8;q++) hist8[q][tid]=0;
    __syncthreads();
    if(tid==0){
        float hx=swmx[0], hn=swmn[0];
        #pragma unroll
        for(int q=1;q<8;q++){ hx=fmaxf(hx,swmx[q]); hn=fminf(hn,swmn[q]); }
        s_lo=hn; s_hi=hx; s_cnt=0;
    }
    __syncthreads();
    float lo=s_lo, hi=s_hi;
    float scale = (hi>lo) ? 255.0f/(hi-lo) : 0.0f;
    int bk[8];
    #pragma unroll
    for(int t=0;t<8;t++){
        int bb = (int)((v[t]-lo)*scale);
        bb = max(0, min(255, bb));
        bk[t]=bb;
        atomicAdd(&hist8[w][bb],1);
    }
    __syncthreads();
    {
        int hsum = 0;
        #pragma unroll
        for(int q=0;q<8;q++) hsum += hist8[q][tid];
        hist[tid] = hsum;
    }
    __syncthreads();
    if(w==0){
        int cs = 0;
        #pragma unroll
        for(int t=0;t<8;t++) cs += hist[lane*8+t];
        int rs = cs;
        #pragma unroll
        for(int o=1;o<32;o<<=1){
            int t2 = __shfl_down_sync(0xffffffffu, rs, o);
            if(lane+o<32) rs += t2;
        }
        int sufx = rs - cs;
        if(rs >= KNB && sufx < KNB){
            int run = sufx, Bv = lane*8;
            for(int j=7;j>=0;j--){
                run += hist[lane*8+j];
                if(run >= KNB){ Bv = lane*8+j; break; }
            }
            s_B = Bv;
        }
    }
    __syncthreads();
    int B = s_B;
    #pragma unroll
    for(int t=0;t<8;t++){
        if(bk[t] >= B){
            int pos = atomicAdd(&s_cnt,1);
            if(pos<256){
                unsigned int u = __float_as_uint(v[t]);
                u = (u & 0x80000000u) ? ~u : (u | 0x80000000u);
                cand[pos] = ((unsigned long long)u<<32) | (unsigned int)(~(base+t));
            }
        }
    }
    __syncthreads();
    int cnt = s_cnt;
    if(cnt<=256){
        if(tid==0){
            int sz = 32;
            while(sz < cnt) sz <<= 1;
            s_size = sz;
        }
        __syncthreads();
        int sz = s_size;
        if(tid<sz && tid>=cnt) cand[tid]=0ull;
        __syncthreads();
        for(int k=2;k<=sz;k<<=1){
            for(int j=k>>1;j>0;j>>=1){
                int ixj = tid ^ j;
                if(ixj > tid && ixj < sz && tid < sz){
                    bool up = ((tid & k) == 0);
                    unsigned long long a=cand[tid], c=cand[ixj];
                    if( (a > c) == up ){ cand[tid]=c; cand[ixj]=a; }
                }
                __syncthreads();
            }
        }
        if(tid<KNB)
            g_idx[((size_t)bq*NN+n)*KNB + tid] = (int)(~(unsigned int)cand[sz-1-tid]);
    } else {
        if(tid==0){
            if(FUSED3){
                int chosen[KNB];
                for(int j=0;j<KNB;j++){
                    float bvv=-FLT_MAX; int bii=0;
                    for(int i=0;i<NN;i++){
                        bool skip=false;
                        for(int q=0;q<j;q++) if(chosen[q]==i){ skip=true; break; }
                        if(skip) continue;
                        float a0=X3[i*3],a1=X3[i*3+1],a2=X3[i*3+2];
                        float ac=__fmaf_rn(X3[n*3],a0,0.f);
                        ac=__fmaf_rn(X3[n*3+1],a1,ac);
                        ac=__fmaf_rn(X3[n*3+2],a2,ac);
                        float vv=__fsub_rn(__fsub_rn(__fmul_rn(2.0f,ac),xxn),xxr[i]);
                        if(vv>bvv){ bvv=vv; bii=i; }
                    }
                    chosen[j]=bii;
                    g_idx[((size_t)bq*NN+n)*KNB + j]=bii;
                }
            } else {
                float* rw = g_dist + ((size_t)bq*NN + n)*NN;
                for(int j=0;j<KNB;j++){
                    float bvv=-FLT_MAX; int bii=0;
                    for(int i=0;i<NN;i++){ float vv=rw[i]; if(vv>bvv){bvv=vv;bii=i;} }
                    g_idx[((size_t)bq*NN+n)*KNB + j]=bii;
                    rw[bii]=-FLT_MAX;
                }
            }
        }
    }
}

__global__ void __launch_bounds__(256) k_topk(){
    int n = blockIdx.x, bq = blockIdx.y;
    const float* row = g_dist + ((size_t)bq*NN + n)*NN;
    int tid = threadIdx.x, lane = tid&31, w = tid>>5;
    float v[8];
    {
        const float4* r4 = (const float4*)(row + tid*8);
        float4 q0 = r4[0], q1 = r4[1];
        v[0]=q0.x; v[1]=q0.y; v[2]=q0.z; v[3]=q0.w;
        v[4]=q1.x; v[5]=q1.y; v[6]=q1.z; v[7]=q1.w;
    }
    topk_select<0>(v, tid, lane, w, n, bq, nullptr, 0.f, nullptr);
}

__global__ void __launch_bounds__(256) k_topk3(){
    int n = blockIdx.x, bq = blockIdx.y;
    const float* X3 = g_xT + (size_t)bq*NN*3;
    const float* xxr = g_xx + (size_t)bq*NN;
    int tid = threadIdx.x, lane = tid&31, w = tid>>5;
    float c0 = X3[n*3], c1 = X3[n*3+1], c2 = X3[n*3+2];
    float xxn = xxr[n];
    float f[24];
    {
        const float4* p4 = (const float4*)(X3 + tid*24);
        #pragma unroll
        for(int q=0;q<6;q++){
            float4 t = p4[q];
            f[q*4+0]=t.x; f[q*4+1]=t.y; f[q*4+2]=t.z; f[q*4+3]=t.w;
        }
    }
    float v[8];
    #pragma unroll
    for(int q=0;q<8;q++){
        float ac = __fmaf_rn(c0, f[q*3+0], 0.f);
        ac = __fmaf_rn(c1, f[q*3+1], ac);
        ac = __fmaf_rn(c2, f[q*3+2], ac);
        v[q] = __fsub_rn(__fsub_rn(__fmul_rn(2.0f, ac), xxn), xxr[tid*8+q]);
    }
    topk_select<1>(v, tid, lane, w, n, bq, X3, xxn, xxr);
}

__global__ void k_ec_stats(int O){
    int o = blockIdx.x, tid = threadIdx.x;
    double s=0.0, ss=0.0;
    for(int b=0;b<BB;b++){
        size_t base = ((size_t)b*O + o)*NN;
        for(int n=tid;n<NN;n+=256){ s += g_ksum[base+n]; ss += g_ksq[base+n]; }
    }
    __shared__ double rs[256], rq[256];
    rs[tid]=s; rq[tid]=ss; __syncthreads();
    for(int st=128;st;st>>=1){ if(tid<st){ rs[tid]+=rs[tid+st]; rq[tid]+=rq[tid+st]; } __syncthreads(); }
    if(tid==0){
        double cnt = (double)BB*NN*KNB;
        double mean = rs[0]/cnt;
        double var  = rq[0]/cnt - mean*mean;
        g_prm[2*o]   = (float)mean;
        g_prm[2*o+1] = (float)var;
    }
}

__global__ void __launch_bounds__(256) k_ec_apply2(int O, int c0, float* __restrict__ xTout,
                            const float* __restrict__ gw, const float* __restrict__ bw){
    int o0 = blockIdx.x*32;
    int n0base = blockIdx.y*256;
    int b = blockIdx.z;
    __shared__ float pmm[32], psd[32], pg[32], pb[32];
    __shared__ int   puse[32];
    __shared__ float tile[64][33];
    int tid = threadIdx.x;
    if(tid<32){
        int o = o0+tid;
        float m = g_prm[2*o], vv = g_prm[2*o+1];
        pmm[tid]=m; psd[tid]=__fsqrt_rn(__fadd_rn(vv, EPSB));
        pg[tid]=gw[o]; pb[tid]=bw[o];
        puse[tid] = (gw[o]>=0.f) ? 1 : 0;
    }
    __syncthreads();
    for(int s=0;s<4;s++){
        int n0 = n0base + s*64;
        #pragma unroll
        for(int e=tid; e<2048; e+=256){
            int ol=e>>6, nl=e&63;
            const float* src = puse[ol] ? g_kmax : g_kmin;
            float vsrc = src[((size_t)b*O + o0+ol)*NN + n0+nl];
            float y = __fadd_rn(__fmul_rn(__fdiv_rn(__fsub_rn(vsrc, pmm[ol]), psd[ol]), pg[ol]), pb[ol]);
            y = (y>=0.f) ? y : __fmul_rn(NEGS, y);
            g_xcat[((size_t)b*512 + c0 + o0+ol)*NN + n0+nl] = y;
            tile[nl][ol] = y;
        }
        __syncthreads();
        #pragma unroll
        for(int e=tid; e<2048; e+=256){
            int nl=e>>5, ol=e&31;
            xTout[((size_t)b*NN + n0+nl)*O + o0+ol] = tile[nl][ol];
        }
        __syncthreads();
    }
}

__global__ void k_conv_stats(const float* __restrict__ h, int O){
    int o = blockIdx.x, tid = threadIdx.x;
    double s=0.0, ss=0.0;
    for(int b=0;b<BB;b++){
        size_t base = ((size_t)b*O + o)*NN;
        for(int n=tid;n<NN;n+=256){ float v=h[base+n]; s += v; ss += (double)v*v; }
    }
    __shared__ double rs[256], rq[256];
    rs[tid]=s; rq[tid]=ss; __syncthreads();
    for(int st=128;st;st>>=1){ if(tid<st){ rs[tid]+=rs[tid+st]; rq[tid]+=rq[tid+st]; } __syncthreads(); }
    if(tid==0){
        double cnt = (double)BB*NN;
        double mean = rs[0]/cnt;
        double var  = rq[0]/cnt - mean*mean;
        g_prm[2*o]   = (float)mean;
        g_prm[2*o+1] = (float)var;
    }
}

__global__ void k_conv_apply(float* __restrict__ h, int O,
                             const float* __restrict__ gw, const float* __restrict__ bw){
    int o = blockIdx.x, b = blockIdx.y;
    float m = g_prm[2*o], vv = g_prm[2*o+1];
    float gg = gw[o], bb = bw[o];
    float sd = __fsqrt_rn(__fadd_rn(vv, EPSB));
    float* p = h + ((size_t)b*O + o)*NN;
    for(int n=threadIdx.x;n<NN;n+=blockDim.x){
        float y = __fadd_rn(__fmul_rn(__fdiv_rn(__fsub_rn(p[n], m), sd), gg), bb);
        p[n] = (y>=0.f) ? y : __fmul_rn(NEGS, y);
    }
}

__global__ void __launch_bounds__(256) k_h5stats(const float* __restrict__ gw,
                                                 const float* __restrict__ bw){
    int o = blockIdx.x, tid = threadIdx.x, lane = tid&31, w = tid>>5;
    double s=0.0, ss=0.0;
    float bmx[BB], bmn[BB];
    #pragma unroll
    for(int b=0;b<BB;b++){ bmx[b]=-FLT_MAX; bmn[b]=FLT_MAX; }
    for(int b=0;b<BB;b++){
        size_t base = ((size_t)b*1024 + o)*NN;
        for(int n=tid;n<NN;n+=256){
            float v = g_h5[base+n];
            s += v; ss += (double)v*v;
            bmx[b]=fmaxf(bmx[b],v); bmn[b]=fminf(bmn[b],v);
        }
    }
    __shared__ double rs[256], rq[256];
    rs[tid]=s; rq[tid]=ss; __syncthreads();
    for(int st=128;st;st>>=1){ if(tid<st){ rs[tid]+=rs[tid+st]; rq[tid]+=rq[tid+st]; } __syncthreads(); }
    __shared__ float sx[8][BB], sn[8][BB];
    #pragma unroll
    for(int b=0;b<BB;b++){
        float mx=bmx[b], mn=bmn[b];
        #pragma unroll
        for(int off=16;off;off>>=1){
            mx=fmaxf(mx,__shfl_xor_sync(0xffffffffu,mx,off));
            mn=fminf(mn,__shfl_xor_sync(0xffffffffu,mn,off));
        }
        if(lane==0){ sx[w][b]=mx; sn[w][b]=mn; }
    }
    __shared__ float smean, svar;
    __syncthreads();
    if(tid==0){
        double cnt = (double)BB*NN;
        double mean = rs[0]/cnt;
        double var  = rq[0]/cnt - mean*mean;
        smean = (float)mean; svar = (float)var;
    }
    __syncthreads();
    if(tid<BB){
        int b = tid;
        float mx=sx[0][b], mn=sn[0][b];
        #pragma unroll
        for(int q=1;q<8;q++){ mx=fmaxf(mx,sx[q][b]); mn=fminf(mn,sn[q][b]); }
        float gg = gw[o];
        float src = (gg>=0.f) ? mx : mn;
        float sd = __fsqrt_rn(__fadd_rn(svar, EPSB));
        float y = __fadd_rn(__fmul_rn(__fdiv_rn(__fsub_rn(src, smean), sd), gg), bw[o]);
        y = (y>=0.f) ? y : __fmul_rn(NEGS, y);
        g_glob[b*1088 + o] = y;
    }
}

__global__ void k_lf(const float* __restrict__ l, const float* __restrict__ W,
                     const float* __restrict__ gw, const float* __restrict__ bw){
    int tid = threadIdx.x;
    int o = tid & 63, b = tid >> 6;
    __shared__ float hs[8][64];
    __shared__ float pm[64], pv[64];
    float s = 0.f;
    #pragma unroll
    for(int c=0;c<16;c++) s = __fmaf_rn(W[o*16 + c], l[b*16 + c], s);
    hs[b][o] = s;
    __syncthreads();
    if(tid < 64){
        float m = 0.f;
        #pragma unroll
        for(int q=0;q<8;q++) m = __fadd_rn(m, hs[q][tid]);
        m = __fdiv_rn(m, 8.f);
        float v = 0.f;
        #pragma unroll
        for(int q=0;q<8;q++){ float d = __fsub_rn(hs[q][tid], m); v = __fmaf_rn(d, d, v); }
        v = __fdiv_rn(v, 8.f);
        pm[tid] = m; pv[tid] = v;
    }
    __syncthreads();
    float sd = __fsqrt_rn(__fadd_rn(pv[o], EPSB));
    float y = __fadd_rn(__fmul_rn(__fdiv_rn(__fsub_rn(hs[b][o], pm[o]), sd), gw[o]), bw[o]);
    y = (y>=0.f) ? y : __fmul_rn(NEGS, y);
    g_glob[b*1088 + 1024 + o] = y;
}

__global__ void k_bias207(const float* __restrict__ W207){
    int b = blockIdx.x;
    __shared__ float gl[1088];
    for(int i=threadIdx.x;i<1088;i+=256) gl[i] = g_glob[b*1088 + i];
    __syncthreads();
    int o = threadIdx.x;
    float s = 0.f;
    for(int c=0;c<1088;c++) s = __fmaf_rn(W207[(size_t)o*1600 + c], gl[c], s);
    g_b207[b*256 + o] = s;
}

// ------------------------- launcher -------------------------
extern "C" void kernel_launch(void* const* d_in, const int* in_sizes, int n_in,
                              void* d_out, int out_size){
    (void)in_sizes; (void)n_in; (void)out_size;
    const float* x    = (const float*)d_in[0];
    const float* l    = (const float*)d_in[1];
    const float* Wec[4] = {(const float*)d_in[2],(const float*)d_in[5],(const float*)d_in[8],(const float*)d_in[11]};
    const float* gec[4] = {(const float*)d_in[3],(const float*)d_in[6],(const float*)d_in[9],(const float*)d_in[12]};
    const float* bec[4] = {(const float*)d_in[4],(const float*)d_in[7],(const float*)d_in[10],(const float*)d_in[13]};
    const float* W5   = (const float*)d_in[14]; const float* g5v  = (const float*)d_in[15]; const float* b5v  = (const float*)d_in[16];
    const float* W206 = (const float*)d_in[17]; const float* g206 = (const float*)d_in[18]; const float* b206 = (const float*)d_in[19];
    const float* W207 = (const float*)d_in[20]; const float* g207 = (const float*)d_in[21]; const float* b207 = (const float*)d_in[22];
    const float* W208 = (const float*)d_in[23]; const float* g208 = (const float*)d_in[24]; const float* b208 = (const float*)d_in[25];
    const float* W209 = (const float*)d_in[26]; const float* g209 = (const float*)d_in[27]; const float* b209 = (const float*)d_in[28];
    const float* W2010= (const float*)d_in[29];

    float *xT,*xxp,*xcat,*h5,*hb1,*hb2,*hb3,*b207p,*basep,*Wdp;
    int *idxp;
    cudaGetSymbolAddress((void**)&xT,   g_xT);
    cudaGetSymbolAddress((void**)&xxp,  g_xx);
    cudaGetSymbolAddress((void**)&idxp, g_idx);
    cudaGetSymbolAddress((void**)&xcat, g_xcat);
    cudaGetSymbolAddress((void**)&h5,   g_h5);
    cudaGetSymbolAddress((void**)&hb1,  g_hb1);
    cudaGetSymbolAddress((void**)&hb2,  g_hb2);
    cudaGetSymbolAddress((void**)&hb3,  g_hb3);
    cudaGetSymbolAddress((void**)&b207p,g_b207);
    cudaGetSymbolAddress((void**)&basep,g_base);
    cudaGetSymbolAddress((void**)&Wdp,  g_Wd);

    const int Cin[4] = {3,64,64,128};
    const int Oo [4] = {64,64,128,256};
    const int c0 [4] = {0,64,128,256};

    k_tin<<<(BB*NN*3 + 255)/256, 256>>>(x);

    for(int li=0; li<4; li++){
        int C = Cin[li], O = Oo[li];
        k_xx<<<(BB*NN + 255)/256, 256>>>(C);
        if(li==0){
            k_topk3<<<dim3(NN, BB), 256>>>();
        } else {
            k_dgemm<<<dim3(NN/128, NN/128, BB), 256>>>(C, xT, xxp);
            k_topk<<<dim3(NN, BB), 256>>>();
        }
        if(li==0){
            k_egemm_t<3,64,3><<<dim3(NN/8, 1, BB), 256>>>(64, Wec[0], xT, idxp);
        } else {
            // split: base = (W_b - W_a) @ ctr, then h = W_a @ nbr + base
            k_wdiff<<<(O*C + 255)/256, 256>>>(Wec[li], O, C);
            k_gemm<false,0><<<dim3(NN/128, (O+127)/128, BB), 256>>>(
                O, NN, C, Wdp, C, 0, xT, C, (size_t)NN*C, basep, (size_t)O*NN, nullptr);
            if(li==1)      k_egemm_s<64, 64,3><<<dim3(NN/8, 1, BB), 256>>>(64,  Wec[1], xT, idxp);
            else if(li==2) k_egemm_s<64,128,2><<<dim3(NN/8, 1, BB), 256>>>(128, Wec[2], xT, idxp);
            else           k_egemm_s<128,128,2><<<dim3(NN/8, 2, BB), 256>>>(256, Wec[3], xT, idxp);
        }
        k_ec_stats<<<O, 256>>>(O);
        k_ec_apply2<<<dim3(O/32, NN/256, BB), 256>>>(O, c0[li], xT, gec[li], bec[li]);
    }

    // ---- continuous tail: 3xTF32 tensor cores (fp32-accurate) ----
    k_tgemm<0><<<dim3(NN/64, 1024/128, BB), 256>>>(
        1024, 512, W5, 512, xcat, (size_t)512*NN, NN, h5, (size_t)1024*NN, nullptr);
    k_h5stats<<<1024, 256>>>(g5v, b5v);
    k_lf<<<1, 512>>>(l, W206, g206, b206);
    k_bias207<<<BB, 256>>>(W207);
    k_tgemm<2><<<dim3(NN/64, 2, BB), 256>>>(
        256, 512, W207 + 1088, 1600, xcat, (size_t)512*NN, NN, hb1, (size_t)256*NN, b207p);
    k_conv_stats<<<256, 256>>>(hb1, 256);
    k_conv_apply<<<dim3(256, BB), 256>>>(hb1, 256, g207, b207);
    k_tgemm<0><<<dim3(NN/64, 2, BB), 256>>>(
        256, 256, W208, 256, hb1, (size_t)256*NN, NN, hb2, (size_t)256*NN, nullptr);
    k_conv_stats<<<256, 256>>>(hb2, 256);
    k_conv_apply<<<dim3(256, BB), 256>>>(hb2, 256, g208, b208);
    k_tgemm<0><<<dim3(NN/64, 1, BB), 256>>>(
        128, 256, W209, 256, hb2, (size_t)256*NN, NN, hb3, (size_t)128*NN, nullptr);
    k_conv_stats<<<128, 256>>>(hb3, 128);
    k_conv_apply<<<dim3(128, BB), 256>>>(hb3, 128, g209, b209);
    k_tgemm<0><<<dim3(NN/64, 1, BB), 256>>>(
        50, 128, W2010, 128, hb3, (size_t)128*NN, NN, (float*)d_out, (size_t)50*NN, nullptr);
}